// round 7
// baseline (speedup 1.0000x reference)
#include <cuda_runtime.h>
#include <cuda_bf16.h>
#include <math.h>

// Problem constants
#define BB 64
#define TT 1024
#define QD 1024
#define CD 512
#define SPLITS 32
#define TCHUNK (TT / SPLITS)   // 32

// Output layout (float32): context[B,CD] | a[B,T] | u_new[B] | sq_new[B]
#define CTX_OFF 0
#define A_OFF   (BB * CD)                 // 32768
#define U_OFF   (A_OFF + BB * TT)         // 98304
#define SQ_OFF  (U_OFF + BB)              // 98368

// Scratch
__device__ float g_partial[BB * SPLITS * CD];   // unnormalized partial contexts
__device__ float g_vsum[BB * SPLITS];           // per-chunk v sums
__device__ float g_hdot[BB * SPLITS * 2];       // per-chunk head-dot partials (u, sq)

__device__ __forceinline__ float alpha_v(
    const float* __restrict__ arow, int t, float ub, float sqb)
{
    const float cur  = arow[t];
    const float prev = (t > 0) ? arow[t - 1] : 0.0f;
    const float base = fmaf(-ub, cur, cur) + fmaf(ub, prev, 1e-6f);
    return __expf(sqb * __logf(base));   // base > 0 always
}

// ---------------------------------------------------------------------------
// K2: fused alpha + split-T partial context + head-dot partials.
// Grid (SPLITS, B), 128 threads. TCHUNK=32 rows of CD floats streamed via
// float4 __ldcs; 2048 blocks -> ~14 blocks/SM for high bytes-in-flight.
// ---------------------------------------------------------------------------
__global__ void __launch_bounds__(128) k_context_partial(
    const float* __restrict__ inputs,
    const float* __restrict__ alpha,
    const float* __restrict__ u,
    const float* __restrict__ sq,
    const float* __restrict__ W_u,
    const float* __restrict__ W_sq,
    float* __restrict__ partial,
    float* __restrict__ vsum,
    float* __restrict__ hdot)
{
    const int s   = blockIdx.x;
    const int b   = blockIdx.y;
    const int tid = threadIdx.x;
    const int t0  = s * TCHUNK;

    __shared__ float sa[TCHUNK];

    if (tid < 32) {  // warp 0: chunk v values + v-sum
        const float ub  = u[b];
        const float sqb = sq[b];
        const float v = alpha_v(alpha + (size_t)b * TT, t0 + tid, ub, sqb);
        sa[tid] = v;
        float x = v;
        #pragma unroll
        for (int o = 16; o > 0; o >>= 1) x += __shfl_xor_sync(0xffffffffu, x, o);
        if (tid == 0) vsum[(size_t)b * SPLITS + s] = x;
    }
    __syncthreads();

    const float4* __restrict__ inp =
        (const float4*)(inputs + ((size_t)b * TT + t0) * CD) + tid;

    float4 a0 = {0,0,0,0}, a1 = {0,0,0,0}, a2 = {0,0,0,0}, a3 = {0,0,0,0};
    #pragma unroll 8
    for (int i = 0; i < TCHUNK; i += 4) {
        const float4 v0 = __ldcs(&inp[(size_t)(i + 0) * (CD/4)]);
        const float4 v1 = __ldcs(&inp[(size_t)(i + 1) * (CD/4)]);
        const float4 v2 = __ldcs(&inp[(size_t)(i + 2) * (CD/4)]);
        const float4 v3 = __ldcs(&inp[(size_t)(i + 3) * (CD/4)]);
        const float w0 = sa[i + 0], w1 = sa[i + 1], w2 = sa[i + 2], w3 = sa[i + 3];
        a0.x = fmaf(w0, v0.x, a0.x); a0.y = fmaf(w0, v0.y, a0.y);
        a0.z = fmaf(w0, v0.z, a0.z); a0.w = fmaf(w0, v0.w, a0.w);
        a1.x = fmaf(w1, v1.x, a1.x); a1.y = fmaf(w1, v1.y, a1.y);
        a1.z = fmaf(w1, v1.z, a1.z); a1.w = fmaf(w1, v1.w, a1.w);
        a2.x = fmaf(w2, v2.x, a2.x); a2.y = fmaf(w2, v2.y, a2.y);
        a2.z = fmaf(w2, v2.z, a2.z); a2.w = fmaf(w2, v2.w, a2.w);
        a3.x = fmaf(w3, v3.x, a3.x); a3.y = fmaf(w3, v3.y, a3.y);
        a3.z = fmaf(w3, v3.z, a3.z); a3.w = fmaf(w3, v3.w, a3.w);
    }
    float4 r;
    r.x = (a0.x + a1.x) + (a2.x + a3.x);
    r.y = (a0.y + a1.y) + (a2.y + a3.y);
    r.z = (a0.z + a1.z) + (a2.z + a3.z);
    r.w = (a0.w + a1.w) + (a2.w + a3.w);
    ((float4*)(partial + ((size_t)b * SPLITS + s) * CD))[tid] = r;

    // head-dot partials vs W_u/W_sq context rows (cols 0..511)
    const float4 wu = ((const float4*)W_u)[tid];
    const float4 ws = ((const float4*)W_sq)[tid];
    float hu = r.x * wu.x + r.y * wu.y + r.z * wu.z + r.w * wu.w;
    float hs = r.x * ws.x + r.y * ws.y + r.z * ws.z + r.w * ws.w;
    #pragma unroll
    for (int o = 16; o > 0; o >>= 1) {
        hu += __shfl_xor_sync(0xffffffffu, hu, o);
        hs += __shfl_xor_sync(0xffffffffu, hs, o);
    }
    __shared__ float ru[4], rs[4];
    if ((tid & 31) == 0) { ru[tid >> 5] = hu; rs[tid >> 5] = hs; }
    __syncthreads();
    if (tid == 0) {
        hdot[((size_t)b * SPLITS + s) * 2 + 0] = (ru[0] + ru[1]) + (ru[2] + ru[3]);
        hdot[((size_t)b * SPLITS + s) * 2 + 1] = (rs[0] + rs[1]) + (rs[2] + rs[3]);
    }
}

// ---------------------------------------------------------------------------
// K3: grid (6, B), 128 threads.
// roles 0..3 : reduce a 128-column slab (8 loads/thread + smem combine).
// role 4     : recompute v, write normalized 'a'.
// role 5     : heads from scalars + query dot.
// ---------------------------------------------------------------------------
__global__ void __launch_bounds__(128) k_finish(
    const float* __restrict__ partial,
    const float* __restrict__ vsum,
    const float* __restrict__ hdot,
    const float* __restrict__ alpha,
    const float* __restrict__ u,
    const float* __restrict__ sq,
    const float* __restrict__ query,
    const float* __restrict__ W_u,  const float* __restrict__ b_u,
    const float* __restrict__ W_sq, const float* __restrict__ b_sq,
    float* __restrict__ out)
{
    const int role = blockIdx.x;
    const int b    = blockIdx.y;
    const int tid  = threadIdx.x;

    // S (every thread; broadcast L2 loads)
    float S = 0.0f;
    #pragma unroll
    for (int k = 0; k < SPLITS; k++) S += vsum[(size_t)b * SPLITS + k];
    const float inv = 1.0f / S;

    if (role < 4) {
        // 128-column slab = 32 float4 groups; 4 thread-slices of 8 splits each.
        const int g  = (tid & 31) + role * 32;          // float4 group in [0,128)
        const int k0 = (tid >> 5) * (SPLITS / 4);
        const float4* __restrict__ p4 =
            (const float4*)(partial + (size_t)b * SPLITS * CD);
        float4 acc = {0,0,0,0};
        #pragma unroll
        for (int k = 0; k < SPLITS / 4; k++) {
            const float4 v = p4[(size_t)(k0 + k) * (CD/4) + g];
            acc.x += v.x; acc.y += v.y; acc.z += v.z; acc.w += v.w;
        }
        __shared__ float4 tmp[128];
        tmp[tid] = acc;
        __syncthreads();
        if (tid < 32) {
            const float4 t0 = tmp[tid],      t1 = tmp[tid + 32];
            const float4 t2 = tmp[tid + 64], t3 = tmp[tid + 96];
            float4 r;
            r.x = ((t0.x + t1.x) + (t2.x + t3.x)) * inv;
            r.y = ((t0.y + t1.y) + (t2.y + t3.y)) * inv;
            r.z = ((t0.z + t1.z) + (t2.z + t3.z)) * inv;
            r.w = ((t0.w + t1.w) + (t2.w + t3.w)) * inv;
            ((float4*)(out + CTX_OFF + (size_t)b * CD))[role * 32 + tid] = r;
        }
        return;
    }

    if (role == 4) {
        // normalized 'a'
        const float ub  = u[b];
        const float sqb = sq[b];
        const float* arow = alpha + (size_t)b * TT;
        #pragma unroll
        for (int t = tid; t < TT; t += 128)
            out[A_OFF + (size_t)b * TT + t] = alpha_v(arow, t, ub, sqb) * inv;
        return;
    }

    // role 5: heads. ctx-part from precomputed hdot scalars; query-part here.
    float hu = 0.0f, hs = 0.0f;
    #pragma unroll
    for (int k = 0; k < SPLITS; k++) {
        hu += hdot[((size_t)b * SPLITS + k) * 2 + 0];
        hs += hdot[((size_t)b * SPLITS + k) * 2 + 1];
    }

    const float4* __restrict__ q4 = (const float4*)(query + (size_t)b * QD);
    float pu = 0.0f, ps = 0.0f;
    #pragma unroll
    for (int j = 0; j < 2; j++) {
        const int i = j * 128 + tid;                  // float4 index into query
        const float4 q  = q4[i];
        const float4 wu = ((const float4*)(W_u  + CD))[i];
        const float4 ws = ((const float4*)(W_sq + CD))[i];
        pu += q.x * wu.x + q.y * wu.y + q.z * wu.z + q.w * wu.w;
        ps += q.x * ws.x + q.y * ws.y + q.z * ws.z + q.w * ws.w;
    }
    #pragma unroll
    for (int o = 16; o > 0; o >>= 1) {
        pu += __shfl_xor_sync(0xffffffffu, pu, o);
        ps += __shfl_xor_sync(0xffffffffu, ps, o);
    }
    __shared__ float ru[4], rs[4];
    if ((tid & 31) == 0) { ru[tid >> 5] = pu; rs[tid >> 5] = ps; }
    __syncthreads();
    if (tid == 0) {
        const float PU = hu * inv + (ru[0] + ru[1]) + (ru[2] + ru[3]) + b_u[0];
        const float PS = hs * inv + (rs[0] + rs[1]) + (rs[2] + rs[3]) + b_sq[0];
        out[U_OFF + b]  = 1.0f / (1.0f + expf(-PU));
        out[SQ_OFF + b] = 1.0f / (1.0f + expf(-PS)) + 1.0f;
    }
}

extern "C" void kernel_launch(void* const* d_in, const int* in_sizes, int n_in,
                              void* d_out, int out_size)
{
    const float* query  = (const float*)d_in[0];  // [B,1,QD]
    const float* inputs = (const float*)d_in[1];  // [B,T,CD]
    const float* alpha  = (const float*)d_in[2];  // [B,T]
    const float* u      = (const float*)d_in[3];  // [B,1]
    const float* sq     = (const float*)d_in[4];  // [B,1]
    const float* W_u    = (const float*)d_in[5];  // [QD+CD,1]
    const float* b_u    = (const float*)d_in[6];  // [1]
    const float* W_sq   = (const float*)d_in[7];  // [QD+CD,1]
    const float* b_sq   = (const float*)d_in[8];  // [1]
    float* out = (float*)d_out;

    float* partial;
    float* vsum;
    float* hdot;
    cudaGetSymbolAddress((void**)&partial, g_partial);
    cudaGetSymbolAddress((void**)&vsum, g_vsum);
    cudaGetSymbolAddress((void**)&hdot, g_hdot);

    dim3 g2(SPLITS, BB);
    k_context_partial<<<g2, 128>>>(inputs, alpha, u, sq, W_u, W_sq,
                                   partial, vsum, hdot);

    dim3 g3(6, BB);
    k_finish<<<g3, 128>>>(partial, vsum, hdot, alpha, u, sq, query,
                          W_u, b_u, W_sq, b_sq, out);
}

// round 8
// speedup vs baseline: 1.0272x; 1.0272x over previous
#include <cuda_runtime.h>
#include <cuda_bf16.h>
#include <math.h>

// Problem constants
#define BB 64
#define TT 1024
#define QD 1024
#define CD 512
#define SPLITS 16
#define TCHUNK (TT / SPLITS)   // 64

// Output layout (float32): context[B,CD] | a[B,T] | u_new[B] | sq_new[B]
#define CTX_OFF 0
#define A_OFF   (BB * CD)                 // 32768
#define U_OFF   (A_OFF + BB * TT)         // 98304
#define SQ_OFF  (U_OFF + BB)              // 98368

// Scratch
__device__ float g_partial[BB * SPLITS * CD];   // unnormalized partial contexts
__device__ float g_hdot[BB * SPLITS * 2];       // per-chunk head-dot partials (u, sq)

__device__ __forceinline__ float alpha_v(
    const float* __restrict__ arow, int t, float ub, float sqb)
{
    const float cur  = arow[t];
    const float prev = (t > 0) ? arow[t - 1] : 0.0f;
    const float base = fmaf(-ub, cur, cur) + fmaf(ub, prev, 1e-6f);
    return __expf(sqb * __logf(base));   // base > 0 always
}

// Recompute S = sum_t v[t] for batch b from inputs only (128 threads).
__device__ __forceinline__ float recompute_S(
    const float* __restrict__ alpha, float ub, float sqb, int b,
    int tid, float* red)
{
    const float* arow = alpha + (size_t)b * TT;
    float s = 0.0f;
    #pragma unroll
    for (int t = tid; t < TT; t += 128) s += alpha_v(arow, t, ub, sqb);
    #pragma unroll
    for (int o = 16; o > 0; o >>= 1) s += __shfl_xor_sync(0xffffffffu, s, o);
    if ((tid & 31) == 0) red[tid >> 5] = s;
    __syncthreads();
    return (red[0] + red[1]) + (red[2] + red[3]);
}

// ---------------------------------------------------------------------------
// K2: fused alpha + split-T partial context + head-dot partials.
// Grid (SPLITS, B), 128 threads. Triggers programmatic launch completion.
// ---------------------------------------------------------------------------
__global__ void __launch_bounds__(128) k_context_partial(
    const float* __restrict__ inputs,
    const float* __restrict__ alpha,
    const float* __restrict__ u,
    const float* __restrict__ sq,
    const float* __restrict__ W_u,
    const float* __restrict__ W_sq,
    float* __restrict__ partial,
    float* __restrict__ hdot)
{
    const int s   = blockIdx.x;
    const int b   = blockIdx.y;
    const int tid = threadIdx.x;
    const int t0  = s * TCHUNK;

    __shared__ float sa[TCHUNK];

    if (tid < TCHUNK) {
        const float ub  = u[b];
        const float sqb = sq[b];
        sa[tid] = alpha_v(alpha + (size_t)b * TT, t0 + tid, ub, sqb);
    }
    __syncthreads();

    const float4* __restrict__ inp =
        (const float4*)(inputs + ((size_t)b * TT + t0) * CD) + tid;

    float4 a0 = {0,0,0,0}, a1 = {0,0,0,0}, a2 = {0,0,0,0}, a3 = {0,0,0,0};
    #pragma unroll 4
    for (int i = 0; i < TCHUNK; i += 4) {
        const float4 v0 = __ldcs(&inp[(size_t)(i + 0) * (CD/4)]);
        const float4 v1 = __ldcs(&inp[(size_t)(i + 1) * (CD/4)]);
        const float4 v2 = __ldcs(&inp[(size_t)(i + 2) * (CD/4)]);
        const float4 v3 = __ldcs(&inp[(size_t)(i + 3) * (CD/4)]);
        const float w0 = sa[i + 0], w1 = sa[i + 1], w2 = sa[i + 2], w3 = sa[i + 3];
        a0.x = fmaf(w0, v0.x, a0.x); a0.y = fmaf(w0, v0.y, a0.y);
        a0.z = fmaf(w0, v0.z, a0.z); a0.w = fmaf(w0, v0.w, a0.w);
        a1.x = fmaf(w1, v1.x, a1.x); a1.y = fmaf(w1, v1.y, a1.y);
        a1.z = fmaf(w1, v1.z, a1.z); a1.w = fmaf(w1, v1.w, a1.w);
        a2.x = fmaf(w2, v2.x, a2.x); a2.y = fmaf(w2, v2.y, a2.y);
        a2.z = fmaf(w2, v2.z, a2.z); a2.w = fmaf(w2, v2.w, a2.w);
        a3.x = fmaf(w3, v3.x, a3.x); a3.y = fmaf(w3, v3.y, a3.y);
        a3.z = fmaf(w3, v3.z, a3.z); a3.w = fmaf(w3, v3.w, a3.w);
    }
    float4 r;
    r.x = (a0.x + a1.x) + (a2.x + a3.x);
    r.y = (a0.y + a1.y) + (a2.y + a3.y);
    r.z = (a0.z + a1.z) + (a2.z + a3.z);
    r.w = (a0.w + a1.w) + (a2.w + a3.w);
    ((float4*)(partial + ((size_t)b * SPLITS + s) * CD))[tid] = r;

    // head-dot partials vs W_u/W_sq context rows (cols 0..511)
    const float4 wu = ((const float4*)W_u)[tid];
    const float4 ws = ((const float4*)W_sq)[tid];
    float hu = r.x * wu.x + r.y * wu.y + r.z * wu.z + r.w * wu.w;
    float hs = r.x * ws.x + r.y * ws.y + r.z * ws.z + r.w * ws.w;
    #pragma unroll
    for (int o = 16; o > 0; o >>= 1) {
        hu += __shfl_xor_sync(0xffffffffu, hu, o);
        hs += __shfl_xor_sync(0xffffffffu, hs, o);
    }
    __shared__ float ru[4], rs[4];
    if ((tid & 31) == 0) { ru[tid >> 5] = hu; rs[tid >> 5] = hs; }
    __syncthreads();
    if (tid == 0) {
        hdot[((size_t)b * SPLITS + s) * 2 + 0] = (ru[0] + ru[1]) + (ru[2] + ru[3]);
        hdot[((size_t)b * SPLITS + s) * 2 + 1] = (rs[0] + rs[1]) + (rs[2] + rs[3]);
    }

#if __CUDA_ARCH__ >= 900
    cudaTriggerProgrammaticLaunchCompletion();
#endif
}

// ---------------------------------------------------------------------------
// K3 (PDL secondary): grid (6, B), 128 threads.
// Pre-sync: recompute S from alpha (input-only); role 4 finishes entirely
// pre-sync; role 5 precomputes the query dot. Post-sync work is minimal.
// ---------------------------------------------------------------------------
__global__ void __launch_bounds__(128) k_finish(
    const float* __restrict__ partial,
    const float* __restrict__ hdot,
    const float* __restrict__ alpha,
    const float* __restrict__ u,
    const float* __restrict__ sq,
    const float* __restrict__ query,
    const float* __restrict__ W_u,  const float* __restrict__ b_u,
    const float* __restrict__ W_sq, const float* __restrict__ b_sq,
    float* __restrict__ out)
{
    const int role = blockIdx.x;
    const int b    = blockIdx.y;
    const int tid  = threadIdx.x;

    __shared__ float red[4];

    const float ub  = u[b];
    const float sqb = sq[b];
    const float S   = recompute_S(alpha, ub, sqb, b, tid, red);
    const float inv = 1.0f / S;

    if (role == 4) {
        // normalized 'a' — depends only on inputs; no grid sync needed.
        const float* arow = alpha + (size_t)b * TT;
        #pragma unroll
        for (int t = tid; t < TT; t += 128)
            out[A_OFF + (size_t)b * TT + t] = alpha_v(arow, t, ub, sqb) * inv;
        return;
    }

    if (role == 5) {
        // pre-sync: query-part dot (independent of K2)
        const float4* __restrict__ q4 = (const float4*)(query + (size_t)b * QD);
        float pu = 0.0f, ps = 0.0f;
        #pragma unroll
        for (int j = 0; j < 2; j++) {
            const int i = j * 128 + tid;
            const float4 q  = q4[i];
            const float4 wu = ((const float4*)(W_u  + CD))[i];
            const float4 ws = ((const float4*)(W_sq + CD))[i];
            pu += q.x * wu.x + q.y * wu.y + q.z * wu.z + q.w * wu.w;
            ps += q.x * ws.x + q.y * ws.y + q.z * ws.z + q.w * ws.w;
        }
        #pragma unroll
        for (int o = 16; o > 0; o >>= 1) {
            pu += __shfl_xor_sync(0xffffffffu, pu, o);
            ps += __shfl_xor_sync(0xffffffffu, ps, o);
        }
        __shared__ float ru[4], rs[4];
        if ((tid & 31) == 0) { ru[tid >> 5] = pu; rs[tid >> 5] = ps; }
        __syncthreads();

#if __CUDA_ARCH__ >= 900
        cudaGridDependencySynchronize();
#endif
        if (tid == 0) {
            float hu = 0.0f, hs = 0.0f;
            #pragma unroll
            for (int k = 0; k < SPLITS; k++) {
                hu += hdot[((size_t)b * SPLITS + k) * 2 + 0];
                hs += hdot[((size_t)b * SPLITS + k) * 2 + 1];
            }
            const float PU = hu * inv + (ru[0] + ru[1]) + (ru[2] + ru[3]) + b_u[0];
            const float PS = hs * inv + (rs[0] + rs[1]) + (rs[2] + rs[3]) + b_sq[0];
            out[U_OFF + b]  = 1.0f / (1.0f + expf(-PU));
            out[SQ_OFF + b] = 1.0f / (1.0f + expf(-PS)) + 1.0f;
        }
        return;
    }

    // roles 0..3: reduce a 128-column slab of the partials.
#if __CUDA_ARCH__ >= 900
    cudaGridDependencySynchronize();
#endif
    const int g  = (tid & 31) + role * 32;          // float4 group in [0,128)
    const int k0 = (tid >> 5) * (SPLITS / 4);
    const float4* __restrict__ p4 =
        (const float4*)(partial + (size_t)b * SPLITS * CD);
    float4 acc = {0,0,0,0};
    #pragma unroll
    for (int k = 0; k < SPLITS / 4; k++) {
        const float4 v = p4[(size_t)(k0 + k) * (CD/4) + g];
        acc.x += v.x; acc.y += v.y; acc.z += v.z; acc.w += v.w;
    }
    __shared__ float4 tmp[128];
    tmp[tid] = acc;
    __syncthreads();
    if (tid < 32) {
        const float4 t0 = tmp[tid],      t1 = tmp[tid + 32];
        const float4 t2 = tmp[tid + 64], t3 = tmp[tid + 96];
        float4 r;
        r.x = ((t0.x + t1.x) + (t2.x + t3.x)) * inv;
        r.y = ((t0.y + t1.y) + (t2.y + t3.y)) * inv;
        r.z = ((t0.z + t1.z) + (t2.z + t3.z)) * inv;
        r.w = ((t0.w + t1.w) + (t2.w + t3.w)) * inv;
        ((float4*)(out + CTX_OFF + (size_t)b * CD))[role * 32 + tid] = r;
    }
}

extern "C" void kernel_launch(void* const* d_in, const int* in_sizes, int n_in,
                              void* d_out, int out_size)
{
    const float* query  = (const float*)d_in[0];  // [B,1,QD]
    const float* inputs = (const float*)d_in[1];  // [B,T,CD]
    const float* alpha  = (const float*)d_in[2];  // [B,T]
    const float* u      = (const float*)d_in[3];  // [B,1]
    const float* sq     = (const float*)d_in[4];  // [B,1]
    const float* W_u    = (const float*)d_in[5];  // [QD+CD,1]
    const float* b_u    = (const float*)d_in[6];  // [1]
    const float* W_sq   = (const float*)d_in[7];  // [QD+CD,1]
    const float* b_sq   = (const float*)d_in[8];  // [1]
    float* out = (float*)d_out;

    float* partial;
    float* hdot;
    cudaGetSymbolAddress((void**)&partial, g_partial);
    cudaGetSymbolAddress((void**)&hdot, g_hdot);

    dim3 g2(SPLITS, BB);
    k_context_partial<<<g2, 128>>>(inputs, alpha, u, sq, W_u, W_sq,
                                   partial, hdot);

    // Secondary launch with programmatic dependent launch (overlaps K2 tail).
    cudaLaunchConfig_t cfg = {};
    cfg.gridDim  = dim3(6, BB, 1);
    cfg.blockDim = dim3(128, 1, 1);
    cfg.dynamicSmemBytes = 0;
    cfg.stream = 0;
    cudaLaunchAttribute attrs[1];
    attrs[0].id = cudaLaunchAttributeProgrammaticStreamSerialization;
    attrs[0].val.programmaticStreamSerializationAllowed = 1;
    cfg.attrs = attrs;
    cfg.numAttrs = 1;

    cudaLaunchKernelEx(&cfg, k_finish,
                       (const float*)partial, (const float*)hdot,
                       alpha, u, sq, query,
                       W_u, b_u, W_sq, b_sq, out);
}